// round 1
// baseline (speedup 1.0000x reference)
#include <cuda_runtime.h>
#include <cuda_bf16.h>

// Problem constants (fixed by setup_inputs): B=8, D=1024, comp 24x24, orig 96x96,
// KERNEL=STRIDE=4, PAD=0 -> all window slots valid, non-overlapping tiling.
constexpr int B_   = 8;
constexpr int D_   = 1024;
constexpr int CH_  = 24, CW_ = 24;
constexpr int OH_  = 96, OW_ = 96;
constexpr int N_   = CH_ * CW_;     // 576 compressed tokens per batch
constexpr int NB_  = B_ * N_;       // 4608 blocks
constexpr int KER_ = 4;
constexpr int WIN_ = KER_ * KER_;   // 16 window slots
constexpr float EPS_ = 1e-12f;

// Deterministic per-block partial sums (no device allocation allowed).
__device__ float g_partial[NB_];

__global__ __launch_bounds__(512, 3)
void rf_sim_kernel(const float* __restrict__ comp, const float* __restrict__ orig) {
    __shared__ float4 sc[D_ / 4];     // compressed token, 4 KB
    __shared__ float  s_red[16];
    __shared__ float  s_invc;
    __shared__ float  s_sims[16];

    const int blk  = blockIdx.x;      // linear (b, token) index
    const int b    = blk / N_;
    const int t    = blk - b * N_;
    const int Hc   = t / CW_;
    const int Wc   = t - Hc * CW_;

    const int tid  = threadIdx.x;
    const int wid  = tid >> 5;        // 16 warps
    const int lane = tid & 31;

    // --- load c into SMEM (512 threads x float2) + partial ||c||^2 ---
    const float2* c2 = reinterpret_cast<const float2*>(comp + (size_t)blk * D_);
    float2 cv = c2[tid];
    reinterpret_cast<float2*>(sc)[tid] = cv;
    float cc = cv.x * cv.x + cv.y * cv.y;
    #pragma unroll
    for (int o = 16; o > 0; o >>= 1) cc += __shfl_xor_sync(0xffffffffu, cc, o);
    if (lane == 0) s_red[wid] = cc;
    __syncthreads();
    if (tid == 0) {
        float s = 0.f;
        #pragma unroll
        for (int i = 0; i < 16; i++) s += s_red[i];
        s_invc = 1.0f / fmaxf(sqrtf(s), EPS_);
    }
    __syncthreads();
    const float invc = s_invc;

    // --- warp `wid` handles window slot `wid` (dh, dw) ---
    const int dh  = wid >> 2;
    const int dw  = wid & 3;
    const int row = (Hc * KER_ + dh) * OW_ + (Wc * KER_ + dw);
    const float4* r4 = reinterpret_cast<const float4*>(
        orig + ((size_t)b * (OH_ * OW_) + row) * D_);
    const float4* c4 = sc;

    float dot = 0.f, rr = 0.f;
    #pragma unroll
    for (int i = 0; i < 8; i++) {
        float4 r = r4[lane + i * 32];
        float4 c = c4[lane + i * 32];
        dot += r.x * c.x + r.y * c.y + r.z * c.z + r.w * c.w;
        rr  += r.x * r.x + r.y * r.y + r.z * r.z + r.w * r.w;
    }
    #pragma unroll
    for (int o = 16; o > 0; o >>= 1) {
        dot += __shfl_xor_sync(0xffffffffu, dot, o);
        rr  += __shfl_xor_sync(0xffffffffu, rr,  o);
    }
    if (lane == 0) s_sims[wid] = dot * invc / fmaxf(sqrtf(rr), EPS_);
    __syncthreads();

    if (tid == 0) {
        float s = 0.f;
        #pragma unroll
        for (int i = 0; i < 16; i++) s += s_sims[i];
        g_partial[blk] = s;
    }
}

__global__ __launch_bounds__(256)
void finalize_kernel(float* __restrict__ out) {
    __shared__ float s_red[8];
    const int tid = threadIdx.x;
    float s = 0.f;
    for (int i = tid; i < NB_; i += 256) s += g_partial[i];
    #pragma unroll
    for (int o = 16; o > 0; o >>= 1) s += __shfl_xor_sync(0xffffffffu, s, o);
    if ((tid & 31) == 0) s_red[tid >> 5] = s;
    __syncthreads();
    if (tid == 0) {
        float tot = 0.f;
        #pragma unroll
        for (int i = 0; i < 8; i++) tot += s_red[i];
        out[0] = 1.0f - tot / (float)(NB_ * WIN_);
    }
}

extern "C" void kernel_launch(void* const* d_in, const int* in_sizes, int n_in,
                              void* d_out, int out_size) {
    const float* comp = (const float*)d_in[0];
    const float* orig = (const float*)d_in[1];
    rf_sim_kernel<<<NB_, 512>>>(comp, orig);
    finalize_kernel<<<1, 256>>>((float*)d_out);
}

// round 2
// speedup vs baseline: 1.0661x; 1.0661x over previous
#include <cuda_runtime.h>
#include <cuda_bf16.h>

// Problem constants (fixed by setup_inputs): B=8, D=1024, comp 24x24, orig 96x96,
// KERNEL=STRIDE=4, PAD=0 -> all window slots valid, non-overlapping tiling.
constexpr int B_   = 8;
constexpr int D_   = 1024;
constexpr int CH_  = 24, CW_ = 24;
constexpr int OH_  = 96, OW_ = 96;
constexpr int N_   = CH_ * CW_;     // 576 compressed tokens per batch
constexpr int NB_  = B_ * N_;       // 4608 blocks
constexpr int KER_ = 4;
constexpr int WIN_ = KER_ * KER_;   // 16 window slots
constexpr float EPS_ = 1e-12f;

// Zero-initialized device globals; the finishing block resets them so every
// graph replay starts from a clean state (no allocation, no host sync).
__device__ float        g_accum = 0.0f;
__device__ unsigned int g_count = 0u;

__global__ __launch_bounds__(512, 3)
void rf_sim_kernel(const float* __restrict__ comp, const float* __restrict__ orig,
                   float* __restrict__ out) {
    __shared__ float4 sc[D_ / 4];     // compressed token, 4 KB
    __shared__ float  s_red[16];
    __shared__ float  s_invc;
    __shared__ float  s_sims[16];

    const int blk  = blockIdx.x;      // linear (b, token) index
    const int b    = blk / N_;
    const int t    = blk - b * N_;
    const int Hc   = t / CW_;
    const int Wc   = t - Hc * CW_;

    const int tid  = threadIdx.x;
    const int wid  = tid >> 5;        // 16 warps
    const int lane = tid & 31;

    // --- load c into SMEM (512 threads x float2) + partial ||c||^2 ---
    const float2* c2 = reinterpret_cast<const float2*>(comp + (size_t)blk * D_);
    float2 cv = c2[tid];
    reinterpret_cast<float2*>(sc)[tid] = cv;
    float cc = cv.x * cv.x + cv.y * cv.y;
    #pragma unroll
    for (int o = 16; o > 0; o >>= 1) cc += __shfl_xor_sync(0xffffffffu, cc, o);
    if (lane == 0) s_red[wid] = cc;
    __syncthreads();
    if (tid == 0) {
        float s = 0.f;
        #pragma unroll
        for (int i = 0; i < 16; i++) s += s_red[i];
        s_invc = 1.0f / fmaxf(sqrtf(s), EPS_);
    }
    __syncthreads();
    const float invc = s_invc;

    // --- warp `wid` handles window slot `wid` (dh, dw) ---
    const int dh  = wid >> 2;
    const int dw  = wid & 3;
    const int row = (Hc * KER_ + dh) * OW_ + (Wc * KER_ + dw);
    const float4* r4 = reinterpret_cast<const float4*>(
        orig + ((size_t)b * (OH_ * OW_) + row) * D_);
    const float4* c4 = sc;

    float dot = 0.f, rr = 0.f;
    #pragma unroll
    for (int i = 0; i < 8; i++) {
        float4 r = r4[lane + i * 32];
        float4 c = c4[lane + i * 32];
        dot += r.x * c.x + r.y * c.y + r.z * c.z + r.w * c.w;
        rr  += r.x * r.x + r.y * r.y + r.z * r.z + r.w * r.w;
    }
    #pragma unroll
    for (int o = 16; o > 0; o >>= 1) {
        dot += __shfl_xor_sync(0xffffffffu, dot, o);
        rr  += __shfl_xor_sync(0xffffffffu, rr,  o);
    }
    if (lane == 0) s_sims[wid] = dot * invc / fmaxf(sqrtf(rr), EPS_);
    __syncthreads();

    // --- block sum -> global atomic; last finished block writes the loss ---
    if (tid == 0) {
        float s = 0.f;
        #pragma unroll
        for (int i = 0; i < 16; i++) s += s_sims[i];
        atomicAdd(&g_accum, s);
        __threadfence();
        unsigned prev = atomicAdd(&g_count, 1u);
        if (prev == (unsigned)(NB_ - 1)) {
            // All adds are visible (fence before each counter bump).
            float tot = g_accum;
            out[0] = 1.0f - tot / (float)(NB_ * WIN_);
            // Reset for the next graph replay.
            g_accum = 0.0f;
            __threadfence();
            g_count = 0u;
        }
    }
}

extern "C" void kernel_launch(void* const* d_in, const int* in_sizes, int n_in,
                              void* d_out, int out_size) {
    const float* comp = (const float*)d_in[0];
    const float* orig = (const float*)d_in[1];
    rf_sim_kernel<<<NB_, 512>>>(comp, orig, (float*)d_out);
}